// round 2
// baseline (speedup 1.0000x reference)
#include <cuda_runtime.h>
#include <math.h>

#define B_ 4
#define C_ 128
#define T_ 32
#define H_ 24
#define W_ 24
#define M_ 3
#define HW_ (H_*W_)               // 576
#define NPER (B_*C_*T_*HW_)       // 9437184 elements per output tensor

// Scratch (device globals; no allocation allowed)
__device__ float g_qg[B_*T_*C_];     // [b][t][c]  pooled q
__device__ float g_h [B_*T_*C_];     // [b][t][c]  GELU(pre_w @ qg + pre_b)
__device__ float g_alpha[B_*M_*T_];  // [b][m][t]  softmax mixture weights

// ---------------------------------------------------------------------------
// Kernel 1: spatial mean pool of q: qg[b,t,c] = mean_{h,w} q[b,c,t,h,w]
// One block per (b,c,t), 192 threads, coalesced read of 576 contiguous floats.
// ---------------------------------------------------------------------------
__global__ void pool_kernel(const float* __restrict__ q) {
    int idx = blockIdx.x;                 // b*C*T + c*T + t
    int t = idx % T_;
    int c = (idx / T_) % C_;
    int b = idx / (T_ * C_);
    const float* p = q + (size_t)idx * HW_;
    float s = 0.f;
    for (int i = threadIdx.x; i < HW_; i += blockDim.x) s += p[i];
    __shared__ float red[8];
    #pragma unroll
    for (int o = 16; o; o >>= 1) s += __shfl_down_sync(0xffffffffu, s, o);
    if ((threadIdx.x & 31) == 0) red[threadIdx.x >> 5] = s;
    __syncthreads();
    if (threadIdx.x < 32) {
        int nw = blockDim.x >> 5;
        float v = (threadIdx.x < nw) ? red[threadIdx.x] : 0.f;
        #pragma unroll
        for (int o = 4; o; o >>= 1) v += __shfl_down_sync(0xffffffffu, v, o);
        if (threadIdx.x == 0) g_qg[(b * T_ + t) * C_ + c] = v * (1.0f / HW_);
    }
}

// ---------------------------------------------------------------------------
// Kernel 2: h[b,t,o] = GELU_exact( pre_b[o] + sum_c pre_w[o,c]*qg[b,t,c] )
// grid (T, B), 128 threads (one per output channel o).
// ---------------------------------------------------------------------------
__global__ void mixpre_kernel(const float* __restrict__ pre_w,
                              const float* __restrict__ pre_b) {
    int t = blockIdx.x, b = blockIdx.y;
    int o = threadIdx.x;
    __shared__ float sq[C_];
    sq[o] = g_qg[(b * T_ + t) * C_ + o];
    __syncthreads();
    float acc = pre_b[o];
    const float* wr = pre_w + o * C_;
    #pragma unroll 8
    for (int c = 0; c < C_; c++) acc += wr[c] * sq[c];
    // exact GELU: 0.5*x*(1+erf(x/sqrt(2)))
    float g = 0.5f * acc * (1.0f + erff(acc * 0.70710678118654752440f));
    g_h[(b * T_ + t) * C_ + o] = g;
}

// ---------------------------------------------------------------------------
// Kernel 3: causal conv1d C->M over T + softmax over M -> alpha[b,m,t]
// Single block, 128 threads; thread i handles one (b,t).
// ---------------------------------------------------------------------------
__global__ void alpha_kernel(const float* __restrict__ mix_w,
                             const float* __restrict__ mix_b) {
    int i = threadIdx.x;
    if (i >= B_ * T_) return;
    int b = i / T_, t = i % T_;
    float logit[M_];
    #pragma unroll
    for (int m = 0; m < M_; m++) {
        float acc = mix_b[m];
        #pragma unroll
        for (int j = 0; j < 3; j++) {
            int tt = t - 2 + j;
            if (tt >= 0) {
                const float* hp = g_h + (b * T_ + tt) * C_;
                const float* wp = mix_w + m * C_ * 3 + j;
                for (int c = 0; c < C_; c++) acc += wp[c * 3] * hp[c];
            }
        }
        logit[m] = acc;
    }
    float mx = fmaxf(logit[0], fmaxf(logit[1], logit[2]));
    float e0 = expf(logit[0] - mx);
    float e1 = expf(logit[1] - mx);
    float e2 = expf(logit[2] - mx);
    float inv = 1.f / (e0 + e1 + e2);
    g_alpha[(b * M_ + 0) * T_ + t] = e0 * inv;
    g_alpha[(b * M_ + 1) * T_ + t] = e1 * inv;
    g_alpha[(b * M_ + 2) * T_ + t] = e2 * inv;
}

// ---------------------------------------------------------------------------
// Kernel 4: fused mixture depthwise causal 3D conv for BOTH k and v.
// For each (b,t): Weff = sum_m alpha[b,m,t] * W[m,c]  (27 taps each for k,v),
// then out[b,c,t,h,w] = sum_{dt,dh,dw} Weff[dt,dh,dw]*x[b,c,t-2+dt,h-1+dh,w-1+dw]
// (zero pad in time front, zero pad spatially).
//
// Block = (b, c, t-half). 144 threads: thread = (h, w-segment of 4).
// Sliding window of 3 time slices per tensor in smem (26x28 zero-padded).
// Each k/v element loaded from HBM exactly once (within its half; 2-slice
// overlap between halves costs ~6% extra reads).
// ---------------------------------------------------------------------------
#define TT    16      // time steps per block
#define RS    28      // smem row stride (floats), 16B-aligned rows
#define SLICE (26*RS) // 728 floats per padded slice

__global__ __launch_bounds__(144) void conv_kernel(
    const float* __restrict__ kin, const float* __restrict__ vin,
    const float* __restrict__ Wk,  const float* __restrict__ Wv,
    float* __restrict__ out) {
    __shared__ float smem[6 * SLICE + 64];
    float* wf = smem + 6 * SLICE;   // 54 effective weights (27 k + 27 v)

    int ts = blockIdx.x, c = blockIdx.y, b = blockIdx.z;
    int tid = threadIdx.x;
    int h = tid / 6, seg = tid % 6, w0 = seg * 4;

    // zero all slices (provides spatial + temporal zero padding)
    for (int i = tid; i < 6 * SLICE; i += 144) smem[i] = 0.f;

    int t0 = ts * TT;
    size_t bc = (size_t)b * C_ + c;
    const float* kbase = kin + bc * T_ * HW_;
    const float* vbase = vin + bc * T_ * HW_;
    float* okbase = out + bc * T_ * HW_;
    float* ovbase = out + (size_t)NPER + bc * T_ * HW_;
    const float* Wkc = Wk + c * 27;   // + m*C_*27 for branch m
    const float* Wvc = Wv + c * 27;

    int tstart = t0 - 2; if (tstart < 0) tstart = 0;

    for (int tt = tstart; tt < t0 + TT; ++tt) {
        __syncthreads();   // previous compute done before slot overwrite / zeros visible
        {
            // load slice tt into slot tt%3 (both tensors)
            int slot = tt % 3;
            const float4 k4 = *(const float4*)(kbase + (size_t)tt * HW_ + h * W_ + w0);
            const float4 v4 = *(const float4*)(vbase + (size_t)tt * HW_ + h * W_ + w0);
            float* dk = smem + slot * SLICE + (h + 1) * RS + (w0 + 1);
            dk[0] = k4.x; dk[1] = k4.y; dk[2] = k4.z; dk[3] = k4.w;
            float* dv = smem + (3 + slot) * SLICE + (h + 1) * RS + (w0 + 1);
            dv[0] = v4.x; dv[1] = v4.y; dv[2] = v4.z; dv[3] = v4.w;
        }
        if (tt >= t0 && tid < 54) {
            // build effective 27-tap kernels for this t
            float a0 = g_alpha[(b * M_ + 0) * T_ + tt];
            float a1 = g_alpha[(b * M_ + 1) * T_ + tt];
            float a2 = g_alpha[(b * M_ + 2) * T_ + tt];
            int j = (tid < 27) ? tid : tid - 27;
            const float* Wc = (tid < 27) ? Wkc : Wvc;
            wf[tid] = a0 * Wc[j] + a1 * Wc[C_ * 27 + j] + a2 * Wc[2 * C_ * 27 + j];
        }
        __syncthreads();
        if (tt < t0) continue;

        int t = tt;
        float ak0 = 0.f, ak1 = 0.f, ak2 = 0.f, ak3 = 0.f;
        float av0 = 0.f, av1 = 0.f, av2 = 0.f, av3 = 0.f;
        #pragma unroll
        for (int d = 0; d < 3; ++d) {
            // input time t-2+d lives at slot (t-2+d)%3 == (t+d+1)%3
            int slot = (t + d + 1) % 3;
            const float* sk = smem + slot * SLICE;
            const float* sv = smem + (3 + slot) * SLICE;
            #pragma unroll
            for (int dh = 0; dh < 3; ++dh) {
                const float* rk = sk + (h + dh) * RS + w0;  // aligned float4
                float4 fa = *(const float4*)rk;
                float4 fb = *(const float4*)(rk + 4);
                float fk[8] = {fa.x, fa.y, fa.z, fa.w, fb.x, fb.y, fb.z, fb.w};
                const float* rv = sv + (h + dh) * RS + w0;
                float4 ga = *(const float4*)rv;
                float4 gb = *(const float4*)(rv + 4);
                float fv[8] = {ga.x, ga.y, ga.z, ga.w, gb.x, gb.y, gb.z, gb.w};
                #pragma unroll
                for (int dw = 0; dw < 3; ++dw) {
                    float wk = wf[d * 9 + dh * 3 + dw];
                    float wv_ = wf[27 + d * 9 + dh * 3 + dw];
                    ak0 += wk * fk[dw];     ak1 += wk * fk[dw + 1];
                    ak2 += wk * fk[dw + 2]; ak3 += wk * fk[dw + 3];
                    av0 += wv_ * fv[dw];     av1 += wv_ * fv[dw + 1];
                    av2 += wv_ * fv[dw + 2]; av3 += wv_ * fv[dw + 3];
                }
            }
        }
        *(float4*)(okbase + (size_t)t * HW_ + h * W_ + w0) = make_float4(ak0, ak1, ak2, ak3);
        *(float4*)(ovbase + (size_t)t * HW_ + h * W_ + w0) = make_float4(av0, av1, av2, av3);
    }
}

// ---------------------------------------------------------------------------
// Launch
// inputs: 0=q 1=k 2=v 3=Wk 4=Wv 5=pre_w 6=pre_b 7=mix_w 8=mix_b
// output: [k_out (9437184 floats), v_out (9437184 floats)]
// ---------------------------------------------------------------------------
extern "C" void kernel_launch(void* const* d_in, const int* in_sizes, int n_in,
                              void* d_out, int out_size) {
    const float* q     = (const float*)d_in[0];
    const float* k     = (const float*)d_in[1];
    const float* v     = (const float*)d_in[2];
    const float* Wk    = (const float*)d_in[3];
    const float* Wv    = (const float*)d_in[4];
    const float* pre_w = (const float*)d_in[5];
    const float* pre_b = (const float*)d_in[6];
    const float* mix_w = (const float*)d_in[7];
    const float* mix_b = (const float*)d_in[8];
    float* out = (float*)d_out;

    pool_kernel<<<B_ * C_ * T_, 192>>>(q);
    {
        dim3 g(T_, B_);
        mixpre_kernel<<<g, C_>>>(pre_w, pre_b);
    }
    alpha_kernel<<<1, 128>>>(mix_w, mix_b);
    {
        dim3 g(T_ / TT, C_, B_);
        conv_kernel<<<g, 144>>>(k, v, Wk, Wv, out);
    }
}

// round 6
// speedup vs baseline: 2.2625x; 2.2625x over previous
#include <cuda_runtime.h>
#include <math.h>

#define B_ 4
#define C_ 128
#define T_ 32
#define H_ 24
#define W_ 24
#define M_ 3
#define HW_ (H_*W_)               // 576
#define NPER (B_*C_*T_*HW_)       // 9437184 elements per output tensor

// Scratch (device globals; no allocation allowed)
__device__ float g_qg[B_*T_*C_];     // [b][t][c]  pooled q
__device__ float g_alpha[B_*M_*T_];  // [b][m][t]  softmax mixture weights

// ---------------------------------------------------------------------------
// Kernel 1: spatial mean pool of q. One WARP per (b,c,t) slice; 576 = 18*32
// contiguous floats, fully coalesced, shuffle reduce, no __syncthreads.
// ---------------------------------------------------------------------------
__global__ __launch_bounds__(256) void pool_kernel(const float* __restrict__ q) {
    int w = threadIdx.x >> 5, lane = threadIdx.x & 31;
    int idx = blockIdx.x * 8 + w;          // b*C*T + c*T + t
    const float* p = q + (size_t)idx * HW_;
    float s = 0.f;
    #pragma unroll
    for (int i = 0; i < 18; ++i) s += p[lane + i * 32];
    #pragma unroll
    for (int o = 16; o; o >>= 1) s += __shfl_down_sync(0xffffffffu, s, o);
    if (lane == 0) {
        int t = idx % T_, c = (idx / T_) % C_, b = idx / (T_ * C_);
        g_qg[(b * T_ + t) * C_ + c] = s * (1.0f / HW_);
    }
}

// ---------------------------------------------------------------------------
// Kernel 2 (fused): per batch b: h = GELU(pre_w @ qg + pre_b) for all t (kept
// in smem), then causal conv1d C->M + softmax -> alpha[b,m,t].
// grid = B_, 128 threads.
// ---------------------------------------------------------------------------
__global__ __launch_bounds__(128) void mix_kernel(const float* __restrict__ pre_w,
                                                  const float* __restrict__ pre_b,
                                                  const float* __restrict__ mix_w,
                                                  const float* __restrict__ mix_b) {
    int b = blockIdx.x, tid = threadIdx.x;
    __shared__ float sq[T_ * C_];
    __shared__ float sh[T_ * C_];
    __shared__ float lg[M_ * T_];

    #pragma unroll
    for (int t = 0; t < T_; ++t) sq[t * C_ + tid] = g_qg[(b * T_ + t) * C_ + tid];
    __syncthreads();

    float acc[T_];
    float pb = pre_b[tid];
    #pragma unroll
    for (int t = 0; t < T_; ++t) acc[t] = pb;
    for (int c = 0; c < C_; ++c) {
        float wv = pre_w[tid * C_ + c];
        #pragma unroll
        for (int t = 0; t < T_; ++t) acc[t] = fmaf(wv, sq[t * C_ + c], acc[t]);
    }
    #pragma unroll
    for (int t = 0; t < T_; ++t) {
        float x = acc[t];
        sh[t * C_ + tid] = 0.5f * x * (1.0f + erff(x * 0.70710678118654752440f));
    }
    __syncthreads();

    if (tid < 96) {
        int m = tid >> 5, t = tid & 31;
        float a = mix_b[m];
        #pragma unroll
        for (int j = 0; j < 3; ++j) {
            int tt = t - 2 + j;
            if (tt >= 0) {
                const float* hp = sh + tt * C_;
                const float* wp = mix_w + m * C_ * 3 + j;
                #pragma unroll 8
                for (int c = 0; c < C_; ++c) a = fmaf(wp[c * 3], hp[c], a);
            }
        }
        lg[m * T_ + t] = a;
    }
    __syncthreads();
    if (tid < T_) {
        int t = tid;
        float l0 = lg[t], l1 = lg[T_ + t], l2 = lg[2 * T_ + t];
        float mx = fmaxf(l0, fmaxf(l1, l2));
        float e0 = expf(l0 - mx), e1 = expf(l1 - mx), e2 = expf(l2 - mx);
        float inv = 1.f / (e0 + e1 + e2);
        g_alpha[(b * M_ + 0) * T_ + t] = e0 * inv;
        g_alpha[(b * M_ + 1) * T_ + t] = e1 * inv;
        g_alpha[(b * M_ + 2) * T_ + t] = e2 * inv;
    }
}

// ---------------------------------------------------------------------------
// Kernel 3: fused mixture depthwise causal 3D conv for BOTH k and v.
// Per-thread tile: 2 rows x 4 cols x 2 timesteps, both tensors.
// Sliding window of 4 time slices per tensor in smem; each loaded smem row is
// reused across 2 output rows and 2 output times -> 2.0 LDS.128 per output.
// 72 threads (12 h-tiles x 6 w-segs), TT=8 per block.
// ---------------------------------------------------------------------------
#define TT    8
#define RS    28       // padded row stride (floats)
#define SLICE (26*RS)  // 728 floats per padded slice

__global__ __launch_bounds__(72) void conv_kernel(
    const float* __restrict__ kin, const float* __restrict__ vin,
    const float* __restrict__ Wk,  const float* __restrict__ Wv,
    float* __restrict__ out) {
    __shared__ float sm[8 * SLICE + 112];  // 4 k slices, 4 v slices, weights
    float* wf = sm + 8 * SLICE;            // [to][tensor][27]

    int t0 = blockIdx.x * TT;
    int c = blockIdx.y, b = blockIdx.z;
    int tid = threadIdx.x;
    int hi = tid / 6, seg = tid % 6;
    int h0 = hi * 2, w0 = seg * 4;
    int lrow = tid / 3, lcol = (tid % 3) * 8;   // loader mapping: 8 floats each

    size_t bc = (size_t)b * C_ + c;
    const float* kbase = kin + bc * T_ * HW_;
    const float* vbase = vin + bc * T_ * HW_;
    float* okbase = out + bc * T_ * HW_;
    float* ovbase = out + (size_t)NPER + bc * T_ * HW_;
    const float* Wkc = Wk + c * 27;
    const float* Wvc = Wv + c * 27;

    // zero all slices (borders + temporal zero padding), vectorized
    for (int i = tid; i < (8 * SLICE) / 4; i += 72)
        ((float4*)sm)[i] = make_float4(0.f, 0.f, 0.f, 0.f);

    __syncthreads();   // *** zeros fully visible before any data is stored ***

    // prologue: slices t0-2, t0-1
    #pragma unroll
    for (int s = 0; s < 2; ++s) {
        int tt = t0 - 2 + s;
        if (tt >= 0) {
            int slot = tt & 3;
            const float* gk = kbase + (size_t)tt * HW_ + tid * 8;
            const float* gv = vbase + (size_t)tt * HW_ + tid * 8;
            float4 ka = ((const float4*)gk)[0], kb2 = ((const float4*)gk)[1];
            float4 va = ((const float4*)gv)[0], vb2 = ((const float4*)gv)[1];
            float* dk = sm + slot * SLICE + (lrow + 1) * RS + lcol + 1;
            float* dv = sm + (4 + slot) * SLICE + (lrow + 1) * RS + lcol + 1;
            dk[0]=ka.x; dk[1]=ka.y; dk[2]=ka.z; dk[3]=ka.w;
            dk[4]=kb2.x; dk[5]=kb2.y; dk[6]=kb2.z; dk[7]=kb2.w;
            dv[0]=va.x; dv[1]=va.y; dv[2]=va.z; dv[3]=va.w;
            dv[4]=vb2.x; dv[5]=vb2.y; dv[6]=vb2.z; dv[7]=vb2.w;
        }
    }

    #pragma unroll 1
    for (int p = 0; p < TT / 2; ++p) {
        int t = t0 + 2 * p;
        __syncthreads();   // previous pair's reads done before slot overwrite
        // load slices t, t+1 (always in range: t+1 <= t0+TT-1 <= 31)
        #pragma unroll
        for (int s = 0; s < 2; ++s) {
            int tt = t + s;
            int slot = tt & 3;
            const float* gk = kbase + (size_t)tt * HW_ + tid * 8;
            const float* gv = vbase + (size_t)tt * HW_ + tid * 8;
            float4 ka = ((const float4*)gk)[0], kb2 = ((const float4*)gk)[1];
            float4 va = ((const float4*)gv)[0], vb2 = ((const float4*)gv)[1];
            float* dk = sm + slot * SLICE + (lrow + 1) * RS + lcol + 1;
            float* dv = sm + (4 + slot) * SLICE + (lrow + 1) * RS + lcol + 1;
            dk[0]=ka.x; dk[1]=ka.y; dk[2]=ka.z; dk[3]=ka.w;
            dk[4]=kb2.x; dk[5]=kb2.y; dk[6]=kb2.z; dk[7]=kb2.w;
            dv[0]=va.x; dv[1]=va.y; dv[2]=va.z; dv[3]=va.w;
            dv[4]=vb2.x; dv[5]=vb2.y; dv[6]=vb2.z; dv[7]=vb2.w;
        }
        // effective 27-tap kernels for t and t+1 (k and v)
        for (int idx = tid; idx < 108; idx += 72) {
            int to = idx / 54, j = idx % 54, jj = (j < 27) ? j : j - 27;
            int tt = t + to;
            float a0 = g_alpha[(b * M_ + 0) * T_ + tt];
            float a1 = g_alpha[(b * M_ + 1) * T_ + tt];
            float a2 = g_alpha[(b * M_ + 2) * T_ + tt];
            const float* Wc = (j < 27) ? Wkc : Wvc;
            wf[idx] = a0 * Wc[jj] + a1 * Wc[C_ * 27 + jj] + a2 * Wc[2 * C_ * 27 + jj];
        }
        __syncthreads();

        float ak[2][2][4], av[2][2][4];
        #pragma unroll
        for (int i = 0; i < 2; ++i)
            #pragma unroll
            for (int r = 0; r < 2; ++r)
                #pragma unroll
                for (int wi = 0; wi < 4; ++wi) { ak[i][r][wi] = 0.f; av[i][r][wi] = 0.f; }

        #pragma unroll
        for (int si = 0; si < 4; ++si) {
            int slot = (t - 2 + si) & 3;  // -2&3=2, -1&3=3: correct mod-4
            const float* skb = sm + slot * SLICE;
            const float* svb = sm + (4 + slot) * SLICE;
            #pragma unroll
            for (int ri = 0; ri < 4; ++ri) {
                const float* rkp = skb + (h0 + ri) * RS + w0;  // padded cols w0..w0+7
                float4 f0 = ((const float4*)rkp)[0], f1 = ((const float4*)rkp)[1];
                float rowk[8] = {f0.x,f0.y,f0.z,f0.w,f1.x,f1.y,f1.z,f1.w};
                const float* rvp = svb + (h0 + ri) * RS + w0;
                float4 g0 = ((const float4*)rvp)[0], g1 = ((const float4*)rvp)[1];
                float rowv[8] = {g0.x,g0.y,g0.z,g0.w,g1.x,g1.y,g1.z,g1.w};
                #pragma unroll
                for (int to = 0; to < 2; ++to) {
                    int d = si - to;
                    if (d < 0 || d > 2) continue;       // compile-time after unroll
                    #pragma unroll
                    for (int r = 0; r < 2; ++r) {
                        int dh = ri - r;
                        if (dh < 0 || dh > 2) continue; // compile-time after unroll
                        #pragma unroll
                        for (int dw = 0; dw < 3; ++dw) {
                            float wkk = wf[to * 54 + d * 9 + dh * 3 + dw];
                            float wvv = wf[to * 54 + 27 + d * 9 + dh * 3 + dw];
                            #pragma unroll
                            for (int wi = 0; wi < 4; ++wi) {
                                ak[to][r][wi] = fmaf(wkk, rowk[wi + dw], ak[to][r][wi]);
                                av[to][r][wi] = fmaf(wvv, rowv[wi + dw], av[to][r][wi]);
                            }
                        }
                    }
                }
            }
        }
        #pragma unroll
        for (int to = 0; to < 2; ++to)
            #pragma unroll
            for (int r = 0; r < 2; ++r) {
                size_t off = (size_t)(t + to) * HW_ + (h0 + r) * W_ + w0;
                ((float4*)(okbase + off))[0] =
                    make_float4(ak[to][r][0], ak[to][r][1], ak[to][r][2], ak[to][r][3]);
                ((float4*)(ovbase + off))[0] =
                    make_float4(av[to][r][0], av[to][r][1], av[to][r][2], av[to][r][3]);
            }
    }
}

// ---------------------------------------------------------------------------
// Launch. inputs: 0=q 1=k 2=v 3=Wk 4=Wv 5=pre_w 6=pre_b 7=mix_w 8=mix_b
// ---------------------------------------------------------------------------
extern "C" void kernel_launch(void* const* d_in, const int* in_sizes, int n_in,
                              void* d_out, int out_size) {
    const float* q     = (const float*)d_in[0];
    const float* k     = (const float*)d_in[1];
    const float* v     = (const float*)d_in[2];
    const float* Wk    = (const float*)d_in[3];
    const float* Wv    = (const float*)d_in[4];
    const float* pre_w = (const float*)d_in[5];
    const float* pre_b = (const float*)d_in[6];
    const float* mix_w = (const float*)d_in[7];
    const float* mix_b = (const float*)d_in[8];
    float* out = (float*)d_out;

    pool_kernel<<<(B_ * C_ * T_) / 8, 256>>>(q);
    mix_kernel<<<B_, 128>>>(pre_w, pre_b, mix_w, mix_b);
    {
        dim3 g(T_ / TT, C_, B_);
        conv_kernel<<<g, 72>>>(k, v, Wk, Wv, out);
    }
}